// round 9
// baseline (speedup 1.0000x reference)
#include <cuda_runtime.h>

#define RAD   5
#define HI    256
#define WI    256
#define HWSZ  (HI * WI)

#define TX    32
#define TY    8
#define SW    (TX + 2 * RAD)   /* 42 */
#define SH    (TY + RAD)       /* 13 */
#define NTHR  512              /* 16 warps; two 256-thread groups split the 60 offsets */
#define MAXBLK 4096

__device__ float    p_num[MAXBLK];
__device__ float    p_den[MAXBLK];
__device__ unsigned g_count = 0;

// Compile-time exp (Taylor; |x| <= ~0.7 at the evaluated points)
__host__ __device__ constexpr float cexp_c(double x) {
    double s = 1.0, t = 1.0;
    for (int i = 1; i < 24; ++i) { t *= x / (double)i; s += t; }
    return (float)s;
}

// One forward offset. O in [0,60): O<5 -> (dy=0, dx=O+1); else dy=(O-5)/11+1, dx=(O-5)%11-5.
template <int O>
struct Step {
    static __device__ __forceinline__ void run(const float4* __restrict__ sf,
                                               const float2* __restrict__ sm,
                                               int base,
                                               float px, float py, float pz,
                                               float bp, float cp,
                                               float& a1, float& a2) {
        constexpr int DY = (O < 5) ? 0 : ((O - 5) / 11 + 1);
        constexpr int DX = (O < 5) ? (O + 1) : ((O - 5) % 11 - 5);
        constexpr float GXY = cexp_c(-(double)(DX * DX + DY * DY) / 72.0);
        constexpr float A = 0.9f * GXY;
        constexpr float B = 0.1f * GXY;
        constexpr int SOFF = DY * SW + DX;

        float4 fq = sf[base + SOFF];
        float2 mq = sm[base + SOFF];
        float d0 = fq.x - px;
        float d1 = fq.y - py;
        float d2 = fq.z - pz;
        float s  = fmaf(d2, d2, fmaf(d1, d1, d0 * d0));
        float arg = s * (-72.134752044448170f);   // -50*log2(e)
        float e;
        asm("ex2.approx.f32 %0, %1;" : "=f"(e) : "f"(arg));
        float K = fmaf(A, e, B);            // g_xy*(0.9*exp + 0.1)
        float w = fmaf(fq.w, cp, bp);       // b_p + b_q - 2 b_p b_q, cp = 1-2*b_p
        float t = K * w;
        a1 = fmaf(t, mq.x, a1);             // * ms_q
        a2 = fmaf(t, mq.y, a2);             // * md_q
    }
};

template <int O, int END>
struct Loop {
    static __device__ __forceinline__ void run(const float4* sf, const float2* sm, int base,
                                               float px, float py, float pz,
                                               float bp, float cp, float& a1, float& a2) {
        Step<O>::run(sf, sm, base, px, py, pz, bp, cp, a1, a2);
        Loop<O + 1, END>::run(sf, sm, base, px, py, pz, bp, cp, a1, a2);
    }
};
template <int END>
struct Loop<END, END> {
    static __device__ __forceinline__ void run(const float4*, const float2*, int,
                                               float, float, float, float, float,
                                               float&, float&) {}
};

__global__ void __launch_bounds__(NTHR) k_fused(const float* __restrict__ x,
                                                const float* __restrict__ y,
                                                const float* __restrict__ msrc,
                                                const float* __restrict__ mdst,
                                                float* __restrict__ out,
                                                int nblk) {
    __shared__ float4 sf[SH * SW];
    __shared__ float2 sm[SH * SW];
    __shared__ float red[NTHR / 32];
    __shared__ float red2[NTHR / 32];
    __shared__ int   slast;

    const int tileX = blockIdx.x * TX;
    const int tileY = blockIdx.y * TY;
    const int n = blockIdx.z;
    const int tid = threadIdx.x;
    const int bid = (blockIdx.z * gridDim.y + blockIdx.y) * gridDim.x + blockIdx.x;
    const int nbase = n * HWSZ;
    const float* xb = x + (size_t)n * 3 * HWSZ;

    // Load tile + halo directly from global, computing features on the fly (2 iterations).
    for (int i = tid; i < SH * SW; i += NTHR) {
        int ly = i / SW;
        int lx = i - ly * SW;
        int gy = tileY + ly;
        int gx = tileX + lx - RAD;
        float4 f = make_float4(0.f, 0.f, 0.f, 0.f);
        float2 m = make_float2(0.f, 0.f);
        if (gx >= 0 && gx < WI && gy < HI) {
            int r  = gy * WI + gx;
            f.x = xb[r];
            f.y = xb[HWSZ + r];
            f.z = xb[2 * HWSZ + r];
            float yy = y[nbase + r];
            f.w = 1.0f / (1.0f + __expf(-yy));       // sigmoid
            float ms = msrc[nbase + r];
            if (!(ms == ms) || ms < 1.0f) ms = 0.0f; // NaN->0, <1 -> 0
            float md = mdst[nbase + r];
            if (!(md == md) || md < 1.0f) md = 0.0f;
            m = make_float2(ms, md);
        }
        sf[i] = f;
        sm[i] = m;
    }
    __syncthreads();

    const int pix  = tid & 255;           // pixel id within tile
    const int half = tid >> 8;            // 0: offsets [0,30), 1: offsets [30,60)
    const int tx = pix & 31;
    const int ty = pix >> 5;              // 0..7

    const int base = ty * SW + (tx + RAD);
    float4 fp = sf[base];
    float2 mp = sm[base];
    float cp = 1.0f - 2.0f * fp.w;
    float a1 = 0.0f, a2 = 0.0f;
    if (half == 0)
        Loop<0, 30>::run(sf, sm, base, fp.x, fp.y, fp.z, fp.w, cp, a1, a2);
    else
        Loop<30, 60>::run(sf, sm, base, fp.x, fp.y, fp.z, fp.w, cp, a1, a2);
    // unordered pair counted once, both orderings: md_p*Σt*ms_q + ms_p*Σt*md_q
    float total = mp.y * a1 + mp.x * a2;
    float den   = (half == 0) ? mp.y : 0.0f;   // denom: binarized md, counted once per pixel

    // block reduce num + den (16 warps)
    #pragma unroll
    for (int o = 16; o; o >>= 1) {
        total += __shfl_xor_sync(0xffffffffu, total, o);
        den   += __shfl_xor_sync(0xffffffffu, den, o);
    }
    if ((tid & 31) == 0) { red[tid >> 5] = total; red2[tid >> 5] = den; }
    __syncthreads();
    if (tid == 0) {
        float vn = 0.0f, vd = 0.0f;
        #pragma unroll
        for (int i = 0; i < NTHR / 32; ++i) { vn += red[i]; vd += red2[i]; }
        p_num[bid] = vn;
        p_den[bid] = vd;
        __threadfence();
        unsigned t = atomicAdd(&g_count, 1u);
        slast = (t == (unsigned)(nblk - 1));
    }
    __syncthreads();

    // Last block: reduce all partials, write result, reset counter.
    if (slast) {
        float vn = 0.0f, vd = 0.0f;
        for (int i = tid; i < nblk; i += NTHR) { vn += p_num[i]; vd += p_den[i]; }
        #pragma unroll
        for (int o = 16; o; o >>= 1) {
            vn += __shfl_xor_sync(0xffffffffu, vn, o);
            vd += __shfl_xor_sync(0xffffffffu, vd, o);
        }
        if ((tid & 31) == 0) { red[tid >> 5] = vn; red2[tid >> 5] = vd; }
        __syncthreads();
        if (tid == 0) {
            float fn = 0.0f, fd = 0.0f;
            #pragma unroll
            for (int i = 0; i < NTHR / 32; ++i) { fn += red[i]; fd += red2[i]; }
            out[0] = fn / fmaxf(fd, 1.0f);
            g_count = 0;    // reset for next graph replay (deterministic)
        }
    }
}

extern "C" void kernel_launch(void* const* d_in, const int* in_sizes, int n_in,
                              void* d_out, int out_size) {
    const float* x    = (const float*)d_in[0];
    const float* y    = (const float*)d_in[1];
    const float* msrc = (const float*)d_in[2];
    const float* mdst = (const float*)d_in[3];

    int NHW = in_sizes[1];          // y element count = N*H*W
    int N   = NHW / HWSZ;

    dim3 grid(WI / TX, HI / TY, N);
    int nblk = grid.x * grid.y * grid.z;
    k_fused<<<grid, NTHR>>>(x, y, msrc, mdst, (float*)d_out, nblk);
}

// round 12
// speedup vs baseline: 1.1210x; 1.1210x over previous
#include <cuda_runtime.h>

#define RAD   5
#define HI    256
#define WI    256
#define HWSZ  (HI * WI)

#define TX    32
#define TY    8
#define SW    (TX + 2 * RAD)   /* 42 */
#define SH    (TY + RAD)       /* 13 */
#define NTHR  128              /* 4 warps; each thread owns 2 vertically adjacent pixels */
#define MAXBLK 4096

#define CEXP  72.134752044448170f   /* 50*log2(e) */

__device__ float    p_num[MAXBLK];
__device__ float    p_den[MAXBLK];
__device__ unsigned g_count = 0;

// Compile-time exp (Taylor; |x| <= ~0.7 at the evaluated points)
__host__ __device__ constexpr float cexp_c(double x) {
    double s = 1.0, t = 1.0;
    for (int i = 1; i < 24; ++i) { t *= x / (double)i; s += t; }
    return (float)s;
}

__device__ __forceinline__ float ex2f(float a) {
    float r; asm("ex2.approx.f32 %0, %1;" : "=f"(r) : "f"(a)); return r;
}

// Per-pixel forward-pair math, dot-product form + 4-way accumulate.
// fq = {x, y, z, cn_q}, mq = {ms, b*ms, md, b*md}
// pxs/pys/pzs = 2c*p, cnp = -c*|p|^2.  K = g_xy*(0.9*exp(-50|q-p|^2) + 0.1).
__device__ __forceinline__ void px_step(float4 fq, float4 mq,
                                        float pxs, float pys, float pzs, float cnp,
                                        float A, float B,
                                        float& S1, float& S2, float& S3, float& S4) {
    float h   = cnp + fq.w;
    float arg = fmaf(fq.x, pxs, fmaf(fq.y, pys, fmaf(fq.z, pzs, h)));
    float e   = ex2f(arg);
    float K   = fmaf(A, e, B);
    S1 = fmaf(K, mq.x, S1);
    S2 = fmaf(K, mq.y, S2);
    S3 = fmaf(K, mq.z, S3);
    S4 = fmaf(K, mq.w, S4);
}

// One shared load at row-offset K_ (0..6), col-offset DX serves:
//   pixel0 (row 2wy)   as dy=K_    (forward if K_ in [1,5], or K_==0 && DX>0)
//   pixel1 (row 2wy+1) as dy=K_-1  (forward if K_ in [2,6], or K_==1 && DX>0)
template <int L>
struct Step2 {
    static __device__ __forceinline__ void run(const float4* __restrict__ sf,
                                               const float4* __restrict__ sm,
                                               int base0,
                                               float p0xs, float p0ys, float p0zs, float cn0,
                                               float p1xs, float p1ys, float p1zs, float cn1,
                                               float& S10, float& S20, float& S30, float& S40,
                                               float& S11, float& S21, float& S31, float& S41) {
        constexpr int K_ = L / 11;
        constexpr int DX = L % 11 - 5;
        constexpr bool LOADQ = (K_ > 0) || (DX > 0);
        constexpr bool P0 = LOADQ && (K_ <= 5);
        constexpr bool P1 = (K_ >= 2) || (K_ == 1 && DX > 0);
        if constexpr (LOADQ) {
            constexpr int SOFF = K_ * SW + DX;
            float4 fq = sf[base0 + SOFF];
            float4 mq = sm[base0 + SOFF];
            if constexpr (P0) {
                constexpr float G = cexp_c(-(double)(DX * DX + K_ * K_) / 72.0);
                px_step(fq, mq, p0xs, p0ys, p0zs, cn0, 0.9f * G, 0.1f * G, S10, S20, S30, S40);
            }
            if constexpr (P1) {
                constexpr int DY1 = K_ - 1;
                constexpr float G = cexp_c(-(double)(DX * DX + DY1 * DY1) / 72.0);
                px_step(fq, mq, p1xs, p1ys, p1zs, cn1, 0.9f * G, 0.1f * G, S11, S21, S31, S41);
            }
        }
    }
};

template <int L, int END>
struct Loop2 {
    static __device__ __forceinline__ void run(const float4* sf, const float4* sm, int base0,
                                               float p0xs, float p0ys, float p0zs, float cn0,
                                               float p1xs, float p1ys, float p1zs, float cn1,
                                               float& S10, float& S20, float& S30, float& S40,
                                               float& S11, float& S21, float& S31, float& S41) {
        Step2<L>::run(sf, sm, base0, p0xs, p0ys, p0zs, cn0, p1xs, p1ys, p1zs, cn1,
                      S10, S20, S30, S40, S11, S21, S31, S41);
        Loop2<L + 1, END>::run(sf, sm, base0, p0xs, p0ys, p0zs, cn0, p1xs, p1ys, p1zs, cn1,
                               S10, S20, S30, S40, S11, S21, S31, S41);
    }
};
template <int END>
struct Loop2<END, END> {
    static __device__ __forceinline__ void run(const float4*, const float4*, int,
                                               float, float, float, float,
                                               float, float, float, float,
                                               float&, float&, float&, float&,
                                               float&, float&, float&, float&) {}
};

__global__ void __launch_bounds__(NTHR) k_fused(const float* __restrict__ x,
                                                const float* __restrict__ y,
                                                const float* __restrict__ msrc,
                                                const float* __restrict__ mdst,
                                                float* __restrict__ out,
                                                int nblk) {
    __shared__ float4 sf[SH * SW];   // {x, y, z, -c*|x|^2}
    __shared__ float4 sm[SH * SW];   // {ms, b*ms, md, b*md}
    __shared__ float  sb[SH * SW];   // b = sigmoid(y)
    __shared__ float  red[NTHR / 32];
    __shared__ float  red2[NTHR / 32];
    __shared__ int    slast;

    const int tileX = blockIdx.x * TX;
    const int tileY = blockIdx.y * TY;
    const int n = blockIdx.z;
    const int tid = threadIdx.x;
    const int bid = (blockIdx.z * gridDim.y + blockIdx.y) * gridDim.x + blockIdx.x;
    const int nbase = n * HWSZ;
    const float* xb = x + (size_t)n * 3 * HWSZ;

    // Load tile + halo directly from global, computing derived features on the fly.
    for (int i = tid; i < SH * SW; i += NTHR) {
        int ly = i / SW;
        int lx = i - ly * SW;
        int gy = tileY + ly;
        int gx = tileX + lx - RAD;
        float4 f = make_float4(0.f, 0.f, 0.f, 0.f);
        float4 m = make_float4(0.f, 0.f, 0.f, 0.f);
        float  b = 0.0f;
        if (gx >= 0 && gx < WI && gy < HI) {
            int r  = gy * WI + gx;
            f.x = xb[r];
            f.y = xb[HWSZ + r];
            f.z = xb[2 * HWSZ + r];
            f.w = fmaf(f.x, f.x, fmaf(f.y, f.y, f.z * f.z)) * (-CEXP);  // -c*|x|^2
            float yy = y[nbase + r];
            b = 1.0f / (1.0f + __expf(-yy));         // sigmoid
            float ms = msrc[nbase + r];
            if (!(ms == ms) || ms < 1.0f) ms = 0.0f; // NaN->0, <1 -> 0
            float md = mdst[nbase + r];
            if (!(md == md) || md < 1.0f) md = 0.0f;
            m = make_float4(ms, b * ms, md, b * md);
        }
        sf[i] = f;
        sm[i] = m;
        sb[i] = b;
    }
    __syncthreads();

    const int tx = tid & 31;
    const int wy = tid >> 5;              // 0..3 — rows 2*wy and 2*wy+1

    const int base0 = (2 * wy) * SW + (tx + RAD);
    const int base1 = base0 + SW;
    float4 fp0 = sf[base0];
    float4 fp1 = sf[base1];
    // p-side constants: 2c*p and -c*|p|^2 (the latter is fp.w already)
    const float TWO_C = 2.0f * CEXP;
    float p0xs = TWO_C * fp0.x, p0ys = TWO_C * fp0.y, p0zs = TWO_C * fp0.z, cn0 = fp0.w;
    float p1xs = TWO_C * fp1.x, p1ys = TWO_C * fp1.y, p1zs = TWO_C * fp1.z, cn1 = fp1.w;

    float S10 = 0.f, S20 = 0.f, S30 = 0.f, S40 = 0.f;
    float S11 = 0.f, S21 = 0.f, S31 = 0.f, S41 = 0.f;
    Loop2<0, 77>::run(sf, sm, base0,
                      p0xs, p0ys, p0zs, cn0,
                      p1xs, p1ys, p1zs, cn1,
                      S10, S20, S30, S40, S11, S21, S31, S41);

    // Recombine: a1 = Σ K*w*ms_q = b_p*S1 + (1-2b_p)*S2 ; a2 likewise with md.
    float4 mp0 = sm[base0];
    float4 mp1 = sm[base1];
    float b0 = sb[base0], b1 = sb[base1];
    float c0 = 1.0f - 2.0f * b0;
    float c1 = 1.0f - 2.0f * b1;
    float a10 = fmaf(b0, S10, c0 * S20);
    float a20 = fmaf(b0, S30, c0 * S40);
    float a11 = fmaf(b1, S11, c1 * S21);
    float a21 = fmaf(b1, S31, c1 * S41);
    // unordered pair counted once, both orderings: md_p*Σt*ms_q + ms_p*Σt*md_q
    float total = mp0.z * a10 + mp0.x * a20 + mp1.z * a11 + mp1.x * a21;
    float den   = mp0.z + mp1.z;          // denom: binarized md over core pixels

    // block reduce num + den (4 warps)
    #pragma unroll
    for (int o = 16; o; o >>= 1) {
        total += __shfl_xor_sync(0xffffffffu, total, o);
        den   += __shfl_xor_sync(0xffffffffu, den, o);
    }
    if ((tid & 31) == 0) { red[tid >> 5] = total; red2[tid >> 5] = den; }
    __syncthreads();
    if (tid == 0) {
        float vn = 0.0f, vd = 0.0f;
        #pragma unroll
        for (int i = 0; i < NTHR / 32; ++i) { vn += red[i]; vd += red2[i]; }
        p_num[bid] = vn;
        p_den[bid] = vd;
        __threadfence();
        unsigned t = atomicAdd(&g_count, 1u);
        slast = (t == (unsigned)(nblk - 1));
    }
    __syncthreads();

    // Last block: reduce all partials, write result, reset counter.
    if (slast) {
        float vn = 0.0f, vd = 0.0f;
        for (int i = tid; i < nblk; i += NTHR) { vn += p_num[i]; vd += p_den[i]; }
        #pragma unroll
        for (int o = 16; o; o >>= 1) {
            vn += __shfl_xor_sync(0xffffffffu, vn, o);
            vd += __shfl_xor_sync(0xffffffffu, vd, o);
        }
        if ((tid & 31) == 0) { red[tid >> 5] = vn; red2[tid >> 5] = vd; }
        __syncthreads();
        if (tid == 0) {
            float fn = 0.0f, fd = 0.0f;
            #pragma unroll
            for (int i = 0; i < NTHR / 32; ++i) { fn += red[i]; fd += red2[i]; }
            out[0] = fn / fmaxf(fd, 1.0f);
            g_count = 0;    // reset for next graph replay (deterministic)
        }
    }
}

extern "C" void kernel_launch(void* const* d_in, const int* in_sizes, int n_in,
                              void* d_out, int out_size) {
    const float* x    = (const float*)d_in[0];
    const float* y    = (const float*)d_in[1];
    const float* msrc = (const float*)d_in[2];
    const float* mdst = (const float*)d_in[3];

    int NHW = in_sizes[1];          // y element count = N*H*W
    int N   = NHW / HWSZ;

    dim3 grid(WI / TX, HI / TY, N);
    int nblk = grid.x * grid.y * grid.z;
    k_fused<<<grid, NTHR>>>(x, y, msrc, mdst, (float*)d_out, nblk);
}

// round 13
// speedup vs baseline: 1.2941x; 1.1544x over previous
#include <cuda_runtime.h>

#define RAD   5
#define HI    256
#define WI    256
#define HWSZ  (HI * WI)

#define TX    32
#define TY    8
#define SW    (TX + 2 * RAD)   /* 42 */
#define SH    (TY + RAD)       /* 13 */
#define NTHR  128              /* 4 warps; each thread owns 2 vertically adjacent pixels */
#define JW    12               /* 12 float4 spans = 48 cols from tileX-8 */

__device__ float    g_num;
__device__ float    g_den;
__device__ unsigned g_count = 0;

// Compile-time exp (Taylor; |x| <= ~0.7 at the evaluated points)
__host__ __device__ constexpr float cexp_c(double x) {
    double s = 1.0, t = 1.0;
    for (int i = 1; i < 24; ++i) { t *= x / (double)i; s += t; }
    return (float)s;
}

__device__ __forceinline__ float ex2f(float a) {
    float r; asm("ex2.approx.f32 %0, %1;" : "=f"(r) : "f"(a)); return r;
}
__device__ __forceinline__ float rcpf(float a) {
    float r; asm("rcp.approx.f32 %0, %1;" : "=f"(r) : "f"(a)); return r;
}

__device__ __forceinline__ void pair_step(float4 fq, float2 mq,
                                          float px, float py, float pz,
                                          float bp, float cp,
                                          float A, float B,
                                          float& a1, float& a2) {
    float d0 = fq.x - px;
    float d1 = fq.y - py;
    float d2 = fq.z - pz;
    float s  = fmaf(d2, d2, fmaf(d1, d1, d0 * d0));
    float arg = s * (-72.134752044448170f);   // -50*log2(e)
    float e   = ex2f(arg);
    float K = fmaf(A, e, B);            // g_xy*(0.9*exp + 0.1)
    float w = fmaf(fq.w, cp, bp);       // b_p + b_q - 2 b_p b_q, cp = 1-2*b_p
    float t = K * w;
    a1 = fmaf(t, mq.x, a1);             // * ms_q
    a2 = fmaf(t, mq.y, a2);             // * md_q
}

// One shared load at row-offset K_ (0..6), col-offset DX serves:
//   pixel0 (row 2wy)   as dy=K_    (forward if K_ in [1,5], or K_==0 && DX>0)
//   pixel1 (row 2wy+1) as dy=K_-1  (forward if K_ in [2,6], or K_==1 && DX>0)
template <int L>
struct Step2 {
    static __device__ __forceinline__ void run(const float4* __restrict__ sf,
                                               const float2* __restrict__ sm,
                                               int base0,
                                               float p0x, float p0y, float p0z, float b0, float c0,
                                               float p1x, float p1y, float p1z, float b1, float c1,
                                               float& a10, float& a20, float& a11, float& a21) {
        constexpr int K_ = L / 11;
        constexpr int DX = L % 11 - 5;
        constexpr bool LOADQ = (K_ > 0) || (DX > 0);
        constexpr bool P0 = LOADQ && (K_ <= 5);
        constexpr bool P1 = (K_ >= 2) || (K_ == 1 && DX > 0);
        if constexpr (LOADQ) {
            constexpr int SOFF = K_ * SW + DX;
            float4 fq = sf[base0 + SOFF];
            float2 mq = sm[base0 + SOFF];
            if constexpr (P0) {
                constexpr float G = cexp_c(-(double)(DX * DX + K_ * K_) / 72.0);
                pair_step(fq, mq, p0x, p0y, p0z, b0, c0, 0.9f * G, 0.1f * G, a10, a20);
            }
            if constexpr (P1) {
                constexpr int DY1 = K_ - 1;
                constexpr float G = cexp_c(-(double)(DX * DX + DY1 * DY1) / 72.0);
                pair_step(fq, mq, p1x, p1y, p1z, b1, c1, 0.9f * G, 0.1f * G, a11, a21);
            }
        }
    }
};

template <int L, int END>
struct Loop2 {
    static __device__ __forceinline__ void run(const float4* sf, const float2* sm, int base0,
                                               float p0x, float p0y, float p0z, float b0, float c0,
                                               float p1x, float p1y, float p1z, float b1, float c1,
                                               float& a10, float& a20, float& a11, float& a21) {
        Step2<L>::run(sf, sm, base0, p0x, p0y, p0z, b0, c0, p1x, p1y, p1z, b1, c1,
                      a10, a20, a11, a21);
        Loop2<L + 1, END>::run(sf, sm, base0, p0x, p0y, p0z, b0, c0, p1x, p1y, p1z, b1, c1,
                               a10, a20, a11, a21);
    }
};
template <int END>
struct Loop2<END, END> {
    static __device__ __forceinline__ void run(const float4*, const float2*, int,
                                               float, float, float, float, float,
                                               float, float, float, float, float,
                                               float&, float&, float&, float&) {}
};

__global__ void __launch_bounds__(NTHR) k_fused(const float* __restrict__ x,
                                                const float* __restrict__ y,
                                                const float* __restrict__ msrc,
                                                const float* __restrict__ mdst,
                                                float* __restrict__ out,
                                                int nblk) {
    __shared__ float4 sf[SH * SW];
    __shared__ float2 sm[SH * SW];
    __shared__ float red[NTHR / 32];
    __shared__ float red2[NTHR / 32];

    const int tileX = blockIdx.x * TX;
    const int tileY = blockIdx.y * TY;
    const int n = blockIdx.z;
    const int tid = threadIdx.x;
    const int nbase = n * HWSZ;
    const float* xb  = x + (size_t)n * 3 * HWSZ;
    const float* yp  = y + nbase;
    const float* msp = msrc + nbase;
    const float* mdp = mdst + nbase;

    // Vectorized tile+halo load: 4 consecutive pixels per float4, 16B-aligned spans.
    // Span j covers gx in [tileX-8+4j, tileX-8+4j+4); lx = gx - tileX + RAD covers [0,42) exactly.
    for (int e = tid; e < SH * JW; e += NTHR) {
        int row = e / JW, j = e - row * JW;
        int gy  = tileY + row;
        int gxb = tileX - 8 + 4 * j;
        float4 vx0 = {0,0,0,0}, vx1 = {0,0,0,0}, vx2 = {0,0,0,0};
        float4 vy  = {0,0,0,0}, vms = {0,0,0,0}, vmd = {0,0,0,0};
        bool rowok = (gy < HI);
        if (rowok && gxb >= 0 && gxb + 4 <= WI) {
            int r = gy * WI + gxb;
            vx0 = *(const float4*)(xb + r);
            vx1 = *(const float4*)(xb + HWSZ + r);
            vx2 = *(const float4*)(xb + 2 * HWSZ + r);
            vy  = *(const float4*)(yp + r);
            vms = *(const float4*)(msp + r);
            vmd = *(const float4*)(mdp + r);
        } else if (rowok) {
            #pragma unroll
            for (int k = 0; k < 4; ++k) {
                int gx = gxb + k;
                if (gx >= 0 && gx < WI) {
                    int r = gy * WI + gx;
                    ((float*)&vx0)[k] = xb[r];
                    ((float*)&vx1)[k] = xb[HWSZ + r];
                    ((float*)&vx2)[k] = xb[2 * HWSZ + r];
                    ((float*)&vy )[k] = yp[r];
                    ((float*)&vms)[k] = msp[r];
                    ((float*)&vmd)[k] = mdp[r];
                }
            }
        }
        #pragma unroll
        for (int k = 0; k < 4; ++k) {
            int gx = gxb + k;
            int lx = gx - tileX + RAD;
            if (lx < 0 || lx >= SW) continue;
            bool inb = rowok && (gx >= 0) && (gx < WI);
            float yy = ((float*)&vy)[k];
            float b  = rcpf(1.0f + ex2f(yy * (-1.4426950408889634f)));  // sigmoid
            float ms = ((float*)&vms)[k];
            if (!(ms == ms) || ms < 1.0f) ms = 0.0f;   // NaN->0, <1 -> 0
            float md = ((float*)&vmd)[k];
            if (!(md == md) || md < 1.0f) md = 0.0f;
            if (!inb) { ms = 0.0f; md = 0.0f; }
            int si = row * SW + lx;
            sf[si] = make_float4(((float*)&vx0)[k], ((float*)&vx1)[k], ((float*)&vx2)[k], b);
            sm[si] = make_float2(ms, md);
        }
    }
    __syncthreads();

    const int tx = tid & 31;
    const int wy = tid >> 5;              // 0..3 — rows 2*wy and 2*wy+1

    const int base0 = (2 * wy) * SW + (tx + RAD);
    const int base1 = base0 + SW;
    float4 fp0 = sf[base0];
    float2 mp0 = sm[base0];
    float4 fp1 = sf[base1];
    float2 mp1 = sm[base1];
    float c0 = 1.0f - 2.0f * fp0.w;
    float c1 = 1.0f - 2.0f * fp1.w;
    float a10 = 0.0f, a20 = 0.0f, a11 = 0.0f, a21 = 0.0f;
    Loop2<0, 77>::run(sf, sm, base0,
                      fp0.x, fp0.y, fp0.z, fp0.w, c0,
                      fp1.x, fp1.y, fp1.z, fp1.w, c1,
                      a10, a20, a11, a21);
    // unordered pair counted once, both orderings: md_p*Σt*ms_q + ms_p*Σt*md_q
    float total = mp0.y * a10 + mp0.x * a20 + mp1.y * a11 + mp1.x * a21;
    float den   = mp0.y + mp1.y;          // denom: binarized md over core pixels

    // block reduce num + den (4 warps)
    #pragma unroll
    for (int o = 16; o; o >>= 1) {
        total += __shfl_xor_sync(0xffffffffu, total, o);
        den   += __shfl_xor_sync(0xffffffffu, den, o);
    }
    if ((tid & 31) == 0) { red[tid >> 5] = total; red2[tid >> 5] = den; }
    __syncthreads();
    if (tid == 0) {
        float vn = 0.0f, vd = 0.0f;
        #pragma unroll
        for (int i = 0; i < NTHR / 32; ++i) { vn += red[i]; vd += red2[i]; }
        atomicAdd(&g_num, vn);
        atomicAdd(&g_den, vd);
        __threadfence();
        unsigned t = atomicAdd(&g_count, 1u);
        if (t == (unsigned)(nblk - 1)) {
            // last block: all adds are visible (release via fence, acquire via counter)
            float fn = atomicAdd(&g_num, 0.0f);
            float fd = atomicAdd(&g_den, 0.0f);
            out[0] = fn / fmaxf(fd, 1.0f);
            // reset for next graph replay (ordering vs next launch is implicit:
            // stream serializes kernel completion before the next replay starts)
            g_num = 0.0f;
            g_den = 0.0f;
            __threadfence();
            g_count = 0u;
        }
    }
}

extern "C" void kernel_launch(void* const* d_in, const int* in_sizes, int n_in,
                              void* d_out, int out_size) {
    const float* x    = (const float*)d_in[0];
    const float* y    = (const float*)d_in[1];
    const float* msrc = (const float*)d_in[2];
    const float* mdst = (const float*)d_in[3];

    int NHW = in_sizes[1];          // y element count = N*H*W
    int N   = NHW / HWSZ;

    dim3 grid(WI / TX, HI / TY, N);
    int nblk = grid.x * grid.y * grid.z;
    k_fused<<<grid, NTHR>>>(x, y, msrc, mdst, (float*)d_out, nblk);
}